// round 13
// baseline (speedup 1.0000x reference)
#include <cuda_runtime.h>
#include <cuda_fp16.h>
#include <math.h>

#define D_MODEL 512
#define DFF     2048
#define NH      8
#define DH      64
#define BATCH   4
#define SEQ     2048
#define MROWS   (BATCH*SEQ)   // 8192

// ---------------- scratch (no allocations allowed) ----------------
__device__ __half g_xn [MROWS*D_MODEL];
__device__ __half g_q  [MROWS*D_MODEL];
__device__ __half g_k  [MROWS*D_MODEL];
__device__ __half g_v  [MROWS*D_MODEL];
__device__ float  g_x2 [MROWS*D_MODEL];
__device__ __half g_xn2[MROWS*D_MODEL];
__device__ __half g_h1 [MROWS*DFF];
__device__ __half g_WqT[D_MODEL*D_MODEL];   // [N,K] transposed, fp16 RNE
__device__ __half g_WkT[D_MODEL*D_MODEL];
__device__ __half g_WvT[D_MODEL*D_MODEL];
__device__ __half g_W1T[DFF*D_MODEL];
__device__ __half g_W2T[D_MODEL*DFF];

// ---------------- helpers ----------------
__device__ __forceinline__ unsigned sw128(unsigned o) { return o ^ ((o >> 3) & 0x70); }

__device__ __forceinline__ void cp_async16(unsigned smem, const void* gptr) {
    asm volatile("cp.async.cg.shared.global [%0], [%1], 16;\n" :: "r"(smem), "l"(gptr));
}
__device__ __forceinline__ void cp_commit() { asm volatile("cp.async.commit_group;\n"); }
__device__ __forceinline__ void cp_wait0()  { asm volatile("cp.async.wait_group 0;\n"); }
__device__ __forceinline__ void cp_wait1()  { asm volatile("cp.async.wait_group 1;\n"); }
__device__ __forceinline__ void cp_wait2()  { asm volatile("cp.async.wait_group 2;\n"); }

__device__ __forceinline__ void ldsm4(unsigned& r0, unsigned& r1, unsigned& r2, unsigned& r3,
                                      unsigned a) {
    asm volatile("ldmatrix.sync.aligned.m8n8.x4.shared.b16 {%0,%1,%2,%3}, [%4];"
                 : "=r"(r0), "=r"(r1), "=r"(r2), "=r"(r3) : "r"(a));
}
__device__ __forceinline__ void ldsm4t(unsigned& r0, unsigned& r1, unsigned& r2, unsigned& r3,
                                       unsigned a) {
    asm volatile("ldmatrix.sync.aligned.m8n8.x4.trans.shared.b16 {%0,%1,%2,%3}, [%4];"
                 : "=r"(r0), "=r"(r1), "=r"(r2), "=r"(r3) : "r"(a));
}
__device__ __forceinline__ void mma_f16(float* c, const unsigned* a, const unsigned* b) {
    asm volatile(
        "mma.sync.aligned.m16n8k16.row.col.f32.f16.f16.f32 "
        "{%0,%1,%2,%3}, {%4,%5,%6,%7}, {%8,%9}, {%0,%1,%2,%3};\n"
        : "+f"(c[0]), "+f"(c[1]), "+f"(c[2]), "+f"(c[3])
        : "r"(a[0]), "r"(a[1]), "r"(a[2]), "r"(a[3]), "r"(b[0]), "r"(b[1]));
}

// half2 sigmoid via tanh: sigma(z) = 0.5*tanh(z/2) + 0.5.
// q carries scale/2, so the MMA result IS z/2. One MUFU per 2 elements.
__device__ __forceinline__ unsigned sig2(float a, float b) {
    __half2 zh = __floats2half2_rn(a, b);
    unsigned zu = *(unsigned*)&zh, tu;
    asm("tanh.approx.f16x2 %0, %1;" : "=r"(tu) : "r"(zu));
    __half2 th = *(__half2*)&tu;
    const __half2 hf = __floats2half2_rn(0.5f, 0.5f);
    __half2 p = __hfma2(th, hf, hf);
    return *(unsigned*)&p;
}

// ---------------- prepass: all 5 weights, one launch ----------------
__global__ __launch_bounds__(256) void transpose_all_kernel(
    const float* __restrict__ Wq, const float* __restrict__ Wk,
    const float* __restrict__ Wv, const float* __restrict__ W1,
    const float* __restrict__ W2,
    __half* __restrict__ WqT, __half* __restrict__ WkT,
    __half* __restrict__ WvT, __half* __restrict__ W1T,
    __half* __restrict__ W2T)
{
    __shared__ float tb[32][33];
    int id = blockIdx.x;
    const float* W; __half* Wt; int K, N, tile, tpr;
    if (id < 768) {
        int w = id >> 8;
        W  = (w == 0) ? Wq  : (w == 1) ? Wk  : Wv;
        Wt = (w == 0) ? WqT : (w == 1) ? WkT : WvT;
        K = 512; N = 512; tile = id & 255; tpr = 16;
    } else if (id < 1792) {
        W = W1; Wt = W1T; K = 512; N = 2048; tile = id - 768; tpr = 64;
    } else {
        W = W2; Wt = W2T; K = 2048; N = 512; tile = id - 1792; tpr = 16;
    }
    int bn = (tile % tpr) * 32, bk = (tile / tpr) * 32;
    int tx = threadIdx.x & 31, ty = threadIdx.x >> 5;   // 32 x 8
#pragma unroll
    for (int j = 0; j < 4; j++) {
        int kr = ty + j * 8;
        tb[kr][tx] = W[(size_t)(bk + kr) * N + bn + tx];
    }
    __syncthreads();
#pragma unroll
    for (int j = 0; j < 4; j++) {
        int nr = ty + j * 8;
        Wt[(size_t)(bn + nr) * K + bk + tx] = __float2half_rn(tb[tx][nr]);
    }
}

// ---------------- LayerNorm (fp16 RNE output) ----------------
__global__ __launch_bounds__(256) void hstu_ln_kernel(
    const float* __restrict__ x, const float* __restrict__ gamma,
    const float* __restrict__ beta, __half* __restrict__ out)
{
    int row  = blockIdx.x * 8 + threadIdx.y;
    int lane = threadIdx.x;
    const float4* xr = (const float4*)(x + (size_t)row * D_MODEL);
    float4 vv[4];
    float s = 0.f, s2 = 0.f;
#pragma unroll
    for (int i = 0; i < 4; i++) {
        vv[i] = xr[lane + 32*i];
        s  += vv[i].x + vv[i].y + vv[i].z + vv[i].w;
        s2 += vv[i].x*vv[i].x + vv[i].y*vv[i].y + vv[i].z*vv[i].z + vv[i].w*vv[i].w;
    }
#pragma unroll
    for (int o = 16; o > 0; o >>= 1) {
        s  += __shfl_xor_sync(0xffffffffu, s,  o);
        s2 += __shfl_xor_sync(0xffffffffu, s2, o);
    }
    float mu   = s  * (1.0f/D_MODEL);
    float var  = s2 * (1.0f/D_MODEL) - mu*mu;
    float rstd = rsqrtf(var + 1e-5f);
    const float4* gr = (const float4*)gamma;
    const float4* br = (const float4*)beta;
    __half2* orow = (__half2*)(out + (size_t)row * D_MODEL);
#pragma unroll
    for (int i = 0; i < 4; i++) {
        float4 g4 = gr[lane + 32*i];
        float4 b4 = br[lane + 32*i];
        float rx = (vv[i].x - mu) * rstd * g4.x + b4.x;
        float ry = (vv[i].y - mu) * rstd * g4.y + b4.y;
        float rz = (vv[i].z - mu) * rstd * g4.z + b4.z;
        float rw = (vv[i].w - mu) * rstd * g4.w + b4.w;
        orow[(lane + 32*i)*2    ] = __floats2half2_rn(rx, ry);
        orow[(lane + 32*i)*2 + 1] = __floats2half2_rn(rz, rw);
    }
}

// ---------------- fp16 tensor-core GEMM: warp 64x64, 4 warps ----------------
#define GEMM_SMEM 98304   // 3 stages x (16K A + 16K B)

__device__ __forceinline__ void gemm_h_core(
    const __half* __restrict__ A, const __half* __restrict__ Wt,
    const float* __restrict__ bias, const float* __restrict__ resid,
    float* __restrict__ Cf, __half* __restrict__ Ch,
    int N, int K, int relu, float oscale, int bm, int bn)
{
    extern __shared__ __align__(128) char smemc[];
    const unsigned sb = (unsigned)__cvta_generic_to_shared(smemc);
    const unsigned sA = sb, sB = sb + 3*16384;
    const int tid = threadIdx.x, lane = tid & 31, wid = tid >> 5;
    const int g = lane >> 2, t = lane & 3;
    const int quad = lane >> 3, lr = lane & 7;
    const int wm = wid >> 1, wn = wid & 1;

    float acc[4][8][4];
#pragma unroll
    for (int i = 0; i < 4; i++)
#pragma unroll
        for (int j = 0; j < 8; j++)
#pragma unroll
            for (int r = 0; r < 4; r++) acc[i][j][r] = 0.f;

    const int nk = K >> 6;   // BK=64

    auto fill = [&](int ch, int s) {
        const char* Ag = (const char*)(A + (size_t)bm * K + ch * 64);
        const char* Bg = (const char*)(Wt + (size_t)bn * K + ch * 64);
        unsigned dA = sA + s * 16384, dB = sB + s * 16384;
#pragma unroll
        for (int i = 0; i < 8; i++) {
            int idx = i * 128 + tid;
            int r = idx >> 3, u = idx & 7;
            cp_async16(dA + sw128(r*128 + u*16), Ag + (size_t)r * K * 2 + u*16);
        }
#pragma unroll
        for (int i = 0; i < 8; i++) {
            int idx = i * 128 + tid;
            int r = idx >> 3, u = idx & 7;
            cp_async16(dB + sw128(r*128 + u*16), Bg + (size_t)r * K * 2 + u*16);
        }
        cp_commit();
    };

    fill(0, 0);
    fill(1, 1);

    for (int i = 0; i < nk; i++) {
        if (i + 1 < nk) cp_wait1(); else cp_wait0();
        __syncthreads();
        if (i + 2 < nk) fill(i + 2, (i + 2) % 3);
        int s = i % 3;
        unsigned bA = sA + s * 16384, bB = sB + s * 16384;
#pragma unroll
        for (int kk = 0; kk < 4; kk++) {
            unsigned af[4][4], bf[4][4];
#pragma unroll
            for (int mi = 0; mi < 4; mi++) {
                unsigned row = wm*64 + mi*16 + (quad & 1)*8 + lr;
                unsigned ku  = kk*2 + (quad >> 1);
                ldsm4(af[mi][0], af[mi][1], af[mi][2], af[mi][3],
                      bA + sw128(row*128 + ku*16));
            }
#pragma unroll
            for (int nb = 0; nb < 4; nb++) {
                unsigned row = wn*64 + nb*16 + (quad >> 1)*8 + lr;
                unsigned ku  = kk*2 + (quad & 1);
                ldsm4(bf[nb][0], bf[nb][1], bf[nb][2], bf[nb][3],
                      bB + sw128(row*128 + ku*16));
            }
#pragma unroll
            for (int mi = 0; mi < 4; mi++)
#pragma unroll
                for (int nb = 0; nb < 4; nb++) {
                    mma_f16(acc[mi][nb*2+0], af[mi], &bf[nb][0]);
                    mma_f16(acc[mi][nb*2+1], af[mi], &bf[nb][2]);
                }
        }
    }

    // epilogue: warp 64x64 block
#pragma unroll
    for (int mi = 0; mi < 4; mi++) {
#pragma unroll
        for (int ni = 0; ni < 8; ni++) {
            int m0  = bm + wm*64 + mi*16 + g;
            int col = bn + wn*64 + ni*8 + 2*t;
            float b0 = bias[col], b1v = bias[col + 1];
            float v00 = acc[mi][ni][0] + b0, v01 = acc[mi][ni][1] + b1v;
            float v10 = acc[mi][ni][2] + b0, v11 = acc[mi][ni][3] + b1v;
            if (relu) {
                v00 = fmaxf(v00, 0.f); v01 = fmaxf(v01, 0.f);
                v10 = fmaxf(v10, 0.f); v11 = fmaxf(v11, 0.f);
            }
            if (Ch) {
                v00 *= oscale; v01 *= oscale; v10 *= oscale; v11 *= oscale;
                *(__half2*)(Ch + (size_t)m0*N + col)     = __floats2half2_rn(v00, v01);
                *(__half2*)(Ch + (size_t)(m0+8)*N + col) = __floats2half2_rn(v10, v11);
            } else {
                if (resid) {
                    float2 r0 = *(const float2*)(resid + (size_t)m0*N + col);
                    float2 r1 = *(const float2*)(resid + (size_t)(m0+8)*N + col);
                    v00 += r0.x; v01 += r0.y; v10 += r1.x; v11 += r1.y;
                }
                *(float2*)(Cf + (size_t)m0*N + col)     = make_float2(v00, v01);
                *(float2*)(Cf + (size_t)(m0+8)*N + col) = make_float2(v10, v11);
            }
        }
    }
}

__global__ __launch_bounds__(128, 2) void gemm_h_kernel(
    const __half* __restrict__ A, const __half* __restrict__ Wt,
    const float* __restrict__ bias, const float* __restrict__ resid,
    float* __restrict__ Cf, __half* __restrict__ Ch, int N, int K, int relu)
{
    gemm_h_core(A, Wt, bias, resid, Cf, Ch, N, K, relu, 1.0f,
                blockIdx.y * 128, blockIdx.x * 128);
}

struct TriH {
    const __half *W0, *W1, *W2;
    const float  *b0, *b1, *b2;
    __half *o0, *o1, *o2;
    float s0, s1, s2;
};
__global__ __launch_bounds__(128, 2) void gemm_qkv_kernel(
    const __half* __restrict__ A, TriH t)
{
    int z = blockIdx.z;
    const __half* W = (z == 0) ? t.W0 : (z == 1) ? t.W1 : t.W2;
    const float*  b = (z == 0) ? t.b0 : (z == 1) ? t.b1 : t.b2;
    __half*       o = (z == 0) ? t.o0 : (z == 1) ? t.o1 : t.o2;
    float        sc = (z == 0) ? t.s0 : (z == 1) ? t.s1 : t.s2;
    gemm_h_core(A, W, b, (const float*)0, (float*)0, o, D_MODEL, D_MODEL, 0, sc,
                blockIdx.y * 128, blockIdx.x * 128);
}

// ---------------- Sigmoid attention: 32q x 64keys warps, S/PV pipelined ----
// Block = (b, h, 256-query tile). 8 warps; warp w owns q rows [w*32, w*32+32).
// Cross-tile software pipeline: each iteration interleaves PV(kt) with
// S(kt+1) per kc chunk (dense 128-MMA block, no intra-block long deps),
// then one sigmoid block. 4 K/V stages, 3 cp.async groups in flight.
// q carries scale/2 (tanh sigmoid). smem 96KB: Q 32K | K 4x8K | V 4x8K.
#define ATT_SMEM 98304

__global__ __launch_bounds__(256, 1) void hstu_attn_kernel(
    const __half* __restrict__ q, const __half* __restrict__ k,
    const __half* __restrict__ v, const float* __restrict__ xres,
    float* __restrict__ out)
{
    extern __shared__ __align__(128) char smemc[];
    const unsigned sb = (unsigned)__cvta_generic_to_shared(smemc);
    const unsigned sQ = sb, sK = sb + 32768, sV = sb + 32768 + 4*8192;

    const int tid = threadIdx.x, lane = tid & 31, wid = tid >> 5;
    const int g = lane >> 2, t = lane & 3;
    const int quad = lane >> 3, lr = lane & 7;
    const int qt = blockIdx.x, h = blockIdx.y, b = blockIdx.z;

    const size_t base = (size_t)b * SEQ * D_MODEL + (size_t)h * DH;
    const __half* qb = q + base;
    const __half* kb = k + base;
    const __half* vb = v + base;

    auto load_kv = [&](int kt, int s) {
#pragma unroll
        for (int i = 0; i < 2; i++) {
            int idx = i * 256 + tid;
            int r = idx >> 3, u = idx & 7;
            cp_async16(sK + s*8192 + sw128(r*128 + u*16),
                       (const char*)(kb + (size_t)(kt*64 + r) * D_MODEL) + u*16);
        }
#pragma unroll
        for (int i = 0; i < 2; i++) {
            int idx = i * 256 + tid;
            int r = idx >> 3, u = idx & 7;
            cp_async16(sV + s*8192 + sw128(r*128 + u*16),
                       (const char*)(vb + (size_t)(kt*64 + r) * D_MODEL) + u*16);
        }
        cp_commit();
    };

    // prologue: Q tile (256 rows, 32KB) rides with KV0's group; then KV1, KV2.
#pragma unroll
    for (int i = 0; i < 8; i++) {
        int idx = i * 256 + tid;
        int r = idx >> 3, u = idx & 7;
        cp_async16(sQ + sw128(r*128 + u*16),
                   (const char*)(qb + (size_t)(qt*256 + r) * D_MODEL) + u*16);
    }
    load_kv(0, 0);   // group 0 (Q + KV0)
    load_kv(1, 1);   // group 1
    load_kv(2, 2);   // group 2

    // loop-invariant ldsm address components
    // sw128(row*128 + c) = row*128 + (c ^ ((row&7)*16)) for c < 128
    const unsigned q1_16 = (quad & 1) * 16;      // K col sel
    const unsigned q2_16 = (quad >> 1) * 16;     // V col sel
    unsigned kba[4], kxo[4];
#pragma unroll
    for (int ng = 0; ng < 4; ng++) {
        unsigned row = ng*16 + (quad >> 1)*8 + lr;
        kba[ng] = row * 128; kxo[ng] = (row & 7) * 16;
    }
    unsigned vba[4], vxo[4];
#pragma unroll
    for (int kc = 0; kc < 4; kc++) {
        unsigned row = kc*16 + (quad & 1)*8 + lr;
        vba[kc] = row * 128; vxo[kc] = (row & 7) * 16;
    }

    float oacc[2][8][4];
#pragma unroll
    for (int mi = 0; mi < 2; mi++)
#pragma unroll
        for (int j = 0; j < 8; j++)
#pragma unroll
            for (int r = 0; r < 4; r++) oacc[mi][j][r] = 0.f;

    unsigned qf[4][2][4];    // hoisted Q fragments
    unsigned ph[2][4][4];    // sigmoid(P) fragments for current kt
    const int NKT = SEQ / 64;

    // ---- prologue compute: S(0) + sigmoid(0) ----
    cp_wait2();              // Q + KV0 arrived
    __syncthreads();
#pragma unroll
    for (int kk = 0; kk < 4; kk++)
#pragma unroll
        for (int mi = 0; mi < 2; mi++) {
            unsigned row = wid*32 + mi*16 + (quad & 1)*8 + lr;
            unsigned ku  = kk*2 + (quad >> 1);
            ldsm4(qf[kk][mi][0], qf[kk][mi][1], qf[kk][mi][2], qf[kk][mi][3],
                  sQ + sw128(row*128 + ku*16));
        }
    {
        float sacc[2][8][4];
#pragma unroll
        for (int mi = 0; mi < 2; mi++)
#pragma unroll
            for (int j = 0; j < 8; j++)
#pragma unroll
                for (int r = 0; r < 4; r++) sacc[mi][j][r] = 0.f;
#pragma unroll
        for (int kk = 0; kk < 4; kk++) {
            unsigned bf[4][4];
            unsigned kc16 = kk*32 + q1_16;
#pragma unroll
            for (int ng = 0; ng < 4; ng++)
                ldsm4(bf[ng][0], bf[ng][1], bf[ng][2], bf[ng][3],
                      sK + kba[ng] + (kc16 ^ kxo[ng]));
#pragma unroll
            for (int mi = 0; mi < 2; mi++)
#pragma unroll
                for (int ng = 0; ng < 4; ng++) {
                    mma_f16(sacc[mi][2*ng+0], qf[kk][mi], &bf[ng][0]);
                    mma_f16(sacc[mi][2*ng+1], qf[kk][mi], &bf[ng][2]);
                }
        }
#pragma unroll
        for (int mi = 0; mi < 2; mi++)
#pragma unroll
            for (int kc = 0; kc < 4; kc++) {
                ph[mi][kc][0] = sig2(sacc[mi][2*kc][0],   sacc[mi][2*kc][1]);
                ph[mi][kc][1] = sig2(sacc[mi][2*kc][2],   sacc[mi][2*kc][3]);
                ph[mi][kc][2] = sig2(sacc[mi][2*kc+1][0], sacc[mi][2*kc+1][1]);
                ph[mi][kc][3] = sig2(sacc[mi][2*kc+1][2], sacc[mi][2*kc+1][3]);
            }
    }

    // ---- main loop: PV(kt) interleaved with S(kt+1) ----
    for (int kt = 0; kt < NKT; kt++) {
        if (kt + 2 < NKT) cp_wait1(); else cp_wait0();
        __syncthreads();
        if (kt + 3 < NKT) load_kv(kt + 3, (kt + 3) & 3);

        unsigned bV = sV + (kt & 3) * 8192;
        unsigned bK = sK + ((kt + 1) & 3) * 8192;
        const bool doS = (kt + 1 < NKT);

        float sacc[2][8][4];
        if (doS) {
#pragma unroll
            for (int mi = 0; mi < 2; mi++)
#pragma unroll
                for (int j = 0; j < 8; j++)
#pragma unroll
                    for (int r = 0; r < 4; r++) sacc[mi][j][r] = 0.f;
        }

#pragma unroll
        for (int kc = 0; kc < 4; kc++) {
            // PV(kt), chunk kc (16 keys)
            unsigned vf[4][4];
#pragma unroll
            for (int nd = 0; nd < 4; nd++)
                ldsm4t(vf[nd][0], vf[nd][1], vf[nd][2], vf[nd][3],
                       bV + vba[kc] + ((nd*32 + q2_16) ^ vxo[kc]));
#pragma unroll
            for (int mi = 0; mi < 2; mi++)
#pragma unroll
                for (int nd = 0; nd < 4; nd++) {
                    mma_f16(oacc[mi][2*nd+0], ph[mi][kc], &vf[nd][0]);
                    mma_f16(oacc[mi][2*nd+1], ph[mi][kc], &vf[nd][2]);
                }
            // S(kt+1), d-chunk kc
            if (doS) {
                unsigned bf[4][4];
                unsigned kc16 = kc*32 + q1_16;
#pragma unroll
                for (int ng = 0; ng < 4; ng++)
                    ldsm4(bf[ng][0], bf[ng][1], bf[ng][2], bf[ng][3],
                          bK + kba[ng] + (kc16 ^ kxo[ng]));
#pragma unroll
                for (int mi = 0; mi < 2; mi++)
#pragma unroll
                    for (int ng = 0; ng < 4; ng++) {
                        mma_f16(sacc[mi][2*ng+0], qf[kc][mi], &bf[ng][0]);
                        mma_f16(sacc[mi][2*ng+1], qf[kc][mi], &bf[ng][2]);
                    }
            }
        }

        if (doS) {
#pragma unroll
            for (int mi = 0; mi < 2; mi++)
#pragma unroll
                for (int kc = 0; kc < 4; kc++) {
                    ph[mi][kc][0] = sig2(sacc[mi][2*kc][0],   sacc[mi][2*kc][1]);
                    ph[mi][kc][1] = sig2(sacc[mi][2*kc][2],   sacc[mi][2*kc][3]);
                    ph[mi][kc][2] = sig2(sacc[mi][2*kc+1][0], sacc[mi][2*kc+1][1]);
                    ph[mi][kc][3] = sig2(sacc[mi][2*kc+1][2], sacc[mi][2*kc+1][3]);
                }
        }
    }

    // ---- epilogue: x2 = x + attn_out (fp32), warp-private rows ----
#pragma unroll
    for (int mi = 0; mi < 2; mi++) {
        int row0 = qt*256 + wid*32 + mi*16 + g;
#pragma unroll
        for (int nj = 0; nj < 8; nj++) {
            int col = nj*8 + 2*t;
            size_t i0 = base + (size_t)row0 * D_MODEL + col;
            size_t i1 = i0 + 8 * D_MODEL;
            float2 r0 = *(const float2*)(xres + i0);
            float2 r1 = *(const float2*)(xres + i1);
            *(float2*)(out + i0) = make_float2(r0.x + oacc[mi][nj][0],
                                               r0.y + oacc[mi][nj][1]);
            *(float2*)(out + i1) = make_float2(r1.x + oacc[mi][nj][2],
                                               r1.y + oacc[mi][nj][3]);
        }
    }
}

// ---------------- launch ----------------
extern "C" void kernel_launch(void* const* d_in, const int* in_sizes, int n_in,
                              void* d_out, int out_size)
{
    const float* x   = (const float*)d_in[0];
    const float* Wq  = (const float*)d_in[1];
    const float* bq  = (const float*)d_in[2];
    const float* Wk  = (const float*)d_in[3];
    const float* bk  = (const float*)d_in[4];
    const float* Wv  = (const float*)d_in[5];
    const float* bv  = (const float*)d_in[6];
    const float* W1  = (const float*)d_in[7];
    const float* b1  = (const float*)d_in[8];
    const float* W2  = (const float*)d_in[9];
    const float* b2  = (const float*)d_in[10];
    const float* g1  = (const float*)d_in[11];
    const float* be1 = (const float*)d_in[12];
    const float* g2  = (const float*)d_in[13];
    const float* be2 = (const float*)d_in[14];
    float* out = (float*)d_out;

    __half *xn, *qh, *kh, *vh, *xn2, *h1;
    float  *x2;
    __half *WqT, *WkT, *WvT, *W1T, *W2T;
    cudaGetSymbolAddress((void**)&xn,  g_xn);
    cudaGetSymbolAddress((void**)&qh,  g_q);
    cudaGetSymbolAddress((void**)&kh,  g_k);
    cudaGetSymbolAddress((void**)&vh,  g_v);
    cudaGetSymbolAddress((void**)&x2,  g_x2);
    cudaGetSymbolAddress((void**)&xn2, g_xn2);
    cudaGetSymbolAddress((void**)&h1,  g_h1);
    cudaGetSymbolAddress((void**)&WqT, g_WqT);
    cudaGetSymbolAddress((void**)&WkT, g_WkT);
    cudaGetSymbolAddress((void**)&WvT, g_WvT);
    cudaGetSymbolAddress((void**)&W1T, g_W1T);
    cudaGetSymbolAddress((void**)&W2T, g_W2T);

    cudaFuncSetAttribute(gemm_h_kernel,
                         cudaFuncAttributeMaxDynamicSharedMemorySize, GEMM_SMEM);
    cudaFuncSetAttribute(gemm_qkv_kernel,
                         cudaFuncAttributeMaxDynamicSharedMemorySize, GEMM_SMEM);
    cudaFuncSetAttribute(hstu_attn_kernel,
                         cudaFuncAttributeMaxDynamicSharedMemorySize, ATT_SMEM);

    // prepass: transpose + fp16-convert all weights (one launch)
    transpose_all_kernel<<<2816, 256>>>(Wq, Wk, Wv, W1, W2,
                                        WqT, WkT, WvT, W1T, W2T);

    dim3 lnb(32, 8);
    // LN1
    hstu_ln_kernel<<<MROWS/8, lnb>>>(x, g1, be1, xn);
    // QKV projections (merged; q pre-scaled by scale/2 for tanh sigmoid)
    TriH tri;
    tri.W0 = WqT; tri.W1 = WkT; tri.W2 = WvT;
    tri.b0 = bq;  tri.b1 = bk;  tri.b2 = bv;
    tri.o0 = qh;  tri.o1 = kh;  tri.o2 = vh;
    tri.s0 = 0.02209708691207961f; tri.s1 = 1.0f; tri.s2 = 1.0f;
    gemm_qkv_kernel<<<dim3(4, 64, 3), 128, GEMM_SMEM>>>(xn, tri);
    // sigmoid attention + residual
    hstu_attn_kernel<<<dim3(SEQ/256, NH, BATCH), 256, ATT_SMEM>>>(qh, kh, vh, x, x2);
    // LN2
    hstu_ln_kernel<<<MROWS/8, lnb>>>(x2, g2, be2, xn2);
    // FFN
    gemm_h_kernel<<<dim3(16, 64), 128, GEMM_SMEM>>>(xn2, W1T, b1, nullptr, nullptr, h1, 2048, 512, 1);
    gemm_h_kernel<<<dim3(4, 64), 128, GEMM_SMEM>>>(h1, W2T, b2, x2, out, nullptr, 512, 2048, 0);
}

// round 14
// speedup vs baseline: 1.0996x; 1.0996x over previous
#include <cuda_runtime.h>
#include <cuda_fp16.h>
#include <math.h>

#define D_MODEL 512
#define DFF     2048
#define NH      8
#define DH      64
#define BATCH   4
#define SEQ     2048
#define MROWS   (BATCH*SEQ)   // 8192

// ---------------- scratch (no allocations allowed) ----------------
__device__ __half g_xn [MROWS*D_MODEL];
__device__ __half g_q  [MROWS*D_MODEL];
__device__ __half g_k  [MROWS*D_MODEL];
__device__ __half g_v  [MROWS*D_MODEL];
__device__ float  g_x2 [MROWS*D_MODEL];
__device__ __half g_xn2[MROWS*D_MODEL];
__device__ __half g_h1 [MROWS*DFF];
__device__ __half g_WqT[D_MODEL*D_MODEL];   // [N,K] transposed, fp16 RNE
__device__ __half g_WkT[D_MODEL*D_MODEL];
__device__ __half g_WvT[D_MODEL*D_MODEL];
__device__ __half g_W1T[DFF*D_MODEL];
__device__ __half g_W2T[D_MODEL*DFF];

// ---------------- helpers ----------------
__device__ __forceinline__ unsigned sw128(unsigned o) { return o ^ ((o >> 3) & 0x70); }

__device__ __forceinline__ void cp_async16(unsigned smem, const void* gptr) {
    asm volatile("cp.async.cg.shared.global [%0], [%1], 16;\n" :: "r"(smem), "l"(gptr));
}
__device__ __forceinline__ void cp_commit() { asm volatile("cp.async.commit_group;\n"); }
__device__ __forceinline__ void cp_wait0()  { asm volatile("cp.async.wait_group 0;\n"); }
__device__ __forceinline__ void cp_wait1()  { asm volatile("cp.async.wait_group 1;\n"); }

__device__ __forceinline__ void ldsm4(unsigned& r0, unsigned& r1, unsigned& r2, unsigned& r3,
                                      unsigned a) {
    asm volatile("ldmatrix.sync.aligned.m8n8.x4.shared.b16 {%0,%1,%2,%3}, [%4];"
                 : "=r"(r0), "=r"(r1), "=r"(r2), "=r"(r3) : "r"(a));
}
__device__ __forceinline__ void ldsm4t(unsigned& r0, unsigned& r1, unsigned& r2, unsigned& r3,
                                       unsigned a) {
    asm volatile("ldmatrix.sync.aligned.m8n8.x4.trans.shared.b16 {%0,%1,%2,%3}, [%4];"
                 : "=r"(r0), "=r"(r1), "=r"(r2), "=r"(r3) : "r"(a));
}
__device__ __forceinline__ void mma_f16(float* c, const unsigned* a, const unsigned* b) {
    asm volatile(
        "mma.sync.aligned.m16n8k16.row.col.f32.f16.f16.f32 "
        "{%0,%1,%2,%3}, {%4,%5,%6,%7}, {%8,%9}, {%0,%1,%2,%3};\n"
        : "+f"(c[0]), "+f"(c[1]), "+f"(c[2]), "+f"(c[3])
        : "r"(a[0]), "r"(a[1]), "r"(a[2]), "r"(a[3]), "r"(b[0]), "r"(b[1]));
}

// half2 sigmoid via tanh: sigma(z) = 0.5*tanh(z/2) + 0.5.
// q carries scale/2, so the MMA result IS z/2. One MUFU per 2 elements.
__device__ __forceinline__ unsigned sig2(float a, float b) {
    __half2 zh = __floats2half2_rn(a, b);
    unsigned zu = *(unsigned*)&zh, tu;
    asm("tanh.approx.f16x2 %0, %1;" : "=r"(tu) : "r"(zu));
    __half2 th = *(__half2*)&tu;
    const __half2 hf = __floats2half2_rn(0.5f, 0.5f);
    __half2 p = __hfma2(th, hf, hf);
    return *(unsigned*)&p;
}

// ---------------- prepass: all 5 weights, one launch ----------------
__global__ __launch_bounds__(256) void transpose_all_kernel(
    const float* __restrict__ Wq, const float* __restrict__ Wk,
    const float* __restrict__ Wv, const float* __restrict__ W1,
    const float* __restrict__ W2,
    __half* __restrict__ WqT, __half* __restrict__ WkT,
    __half* __restrict__ WvT, __half* __restrict__ W1T,
    __half* __restrict__ W2T)
{
    __shared__ float tb[32][33];
    int id = blockIdx.x;
    const float* W; __half* Wt; int K, N, tile, tpr;
    if (id < 768) {
        int w = id >> 8;
        W  = (w == 0) ? Wq  : (w == 1) ? Wk  : Wv;
        Wt = (w == 0) ? WqT : (w == 1) ? WkT : WvT;
        K = 512; N = 512; tile = id & 255; tpr = 16;
    } else if (id < 1792) {
        W = W1; Wt = W1T; K = 512; N = 2048; tile = id - 768; tpr = 64;
    } else {
        W = W2; Wt = W2T; K = 2048; N = 512; tile = id - 1792; tpr = 16;
    }
    int bn = (tile % tpr) * 32, bk = (tile / tpr) * 32;
    int tx = threadIdx.x & 31, ty = threadIdx.x >> 5;   // 32 x 8
#pragma unroll
    for (int j = 0; j < 4; j++) {
        int kr = ty + j * 8;
        tb[kr][tx] = W[(size_t)(bk + kr) * N + bn + tx];
    }
    __syncthreads();
#pragma unroll
    for (int j = 0; j < 4; j++) {
        int nr = ty + j * 8;
        Wt[(size_t)(bn + nr) * K + bk + tx] = __float2half_rn(tb[tx][nr]);
    }
}

// ---------------- LayerNorm (fp16 RNE output) ----------------
__global__ __launch_bounds__(256) void hstu_ln_kernel(
    const float* __restrict__ x, const float* __restrict__ gamma,
    const float* __restrict__ beta, __half* __restrict__ out)
{
    int row  = blockIdx.x * 8 + threadIdx.y;
    int lane = threadIdx.x;
    const float4* xr = (const float4*)(x + (size_t)row * D_MODEL);
    float4 vv[4];
    float s = 0.f, s2 = 0.f;
#pragma unroll
    for (int i = 0; i < 4; i++) {
        vv[i] = xr[lane + 32*i];
        s  += vv[i].x + vv[i].y + vv[i].z + vv[i].w;
        s2 += vv[i].x*vv[i].x + vv[i].y*vv[i].y + vv[i].z*vv[i].z + vv[i].w*vv[i].w;
    }
#pragma unroll
    for (int o = 16; o > 0; o >>= 1) {
        s  += __shfl_xor_sync(0xffffffffu, s,  o);
        s2 += __shfl_xor_sync(0xffffffffu, s2, o);
    }
    float mu   = s  * (1.0f/D_MODEL);
    float var  = s2 * (1.0f/D_MODEL) - mu*mu;
    float rstd = rsqrtf(var + 1e-5f);
    const float4* gr = (const float4*)gamma;
    const float4* br = (const float4*)beta;
    __half2* orow = (__half2*)(out + (size_t)row * D_MODEL);
#pragma unroll
    for (int i = 0; i < 4; i++) {
        float4 g4 = gr[lane + 32*i];
        float4 b4 = br[lane + 32*i];
        float rx = (vv[i].x - mu) * rstd * g4.x + b4.x;
        float ry = (vv[i].y - mu) * rstd * g4.y + b4.y;
        float rz = (vv[i].z - mu) * rstd * g4.z + b4.z;
        float rw = (vv[i].w - mu) * rstd * g4.w + b4.w;
        orow[(lane + 32*i)*2    ] = __floats2half2_rn(rx, ry);
        orow[(lane + 32*i)*2 + 1] = __floats2half2_rn(rz, rw);
    }
}

// ---------------- fp16 tensor-core GEMM: warp 64x64, 4 warps ----------------
#define GEMM_SMEM 98304   // 3 stages x (16K A + 16K B)

__device__ __forceinline__ void gemm_h_core(
    const __half* __restrict__ A, const __half* __restrict__ Wt,
    const float* __restrict__ bias, const float* __restrict__ resid,
    float* __restrict__ Cf, __half* __restrict__ Ch,
    int N, int K, int relu, float oscale, int bm, int bn)
{
    extern __shared__ __align__(128) char smemc[];
    const unsigned sb = (unsigned)__cvta_generic_to_shared(smemc);
    const unsigned sA = sb, sB = sb + 3*16384;
    const int tid = threadIdx.x, lane = tid & 31, wid = tid >> 5;
    const int g = lane >> 2, t = lane & 3;
    const int quad = lane >> 3, lr = lane & 7;
    const int wm = wid >> 1, wn = wid & 1;

    float acc[4][8][4];
#pragma unroll
    for (int i = 0; i < 4; i++)
#pragma unroll
        for (int j = 0; j < 8; j++)
#pragma unroll
            for (int r = 0; r < 4; r++) acc[i][j][r] = 0.f;

    const int nk = K >> 6;   // BK=64

    auto fill = [&](int ch, int s) {
        const char* Ag = (const char*)(A + (size_t)bm * K + ch * 64);
        const char* Bg = (const char*)(Wt + (size_t)bn * K + ch * 64);
        unsigned dA = sA + s * 16384, dB = sB + s * 16384;
#pragma unroll
        for (int i = 0; i < 8; i++) {
            int idx = i * 128 + tid;
            int r = idx >> 3, u = idx & 7;
            cp_async16(dA + sw128(r*128 + u*16), Ag + (size_t)r * K * 2 + u*16);
        }
#pragma unroll
        for (int i = 0; i < 8; i++) {
            int idx = i * 128 + tid;
            int r = idx >> 3, u = idx & 7;
            cp_async16(dB + sw128(r*128 + u*16), Bg + (size_t)r * K * 2 + u*16);
        }
        cp_commit();
    };

    fill(0, 0);
    fill(1, 1);

    for (int i = 0; i < nk; i++) {
        if (i + 1 < nk) cp_wait1(); else cp_wait0();
        __syncthreads();
        if (i + 2 < nk) fill(i + 2, (i + 2) % 3);
        int s = i % 3;
        unsigned bA = sA + s * 16384, bB = sB + s * 16384;
#pragma unroll
        for (int kk = 0; kk < 4; kk++) {
            unsigned af[4][4], bf[4][4];
#pragma unroll
            for (int mi = 0; mi < 4; mi++) {
                unsigned row = wm*64 + mi*16 + (quad & 1)*8 + lr;
                unsigned ku  = kk*2 + (quad >> 1);
                ldsm4(af[mi][0], af[mi][1], af[mi][2], af[mi][3],
                      bA + sw128(row*128 + ku*16));
            }
#pragma unroll
            for (int nb = 0; nb < 4; nb++) {
                unsigned row = wn*64 + nb*16 + (quad >> 1)*8 + lr;
                unsigned ku  = kk*2 + (quad & 1);
                ldsm4(bf[nb][0], bf[nb][1], bf[nb][2], bf[nb][3],
                      bB + sw128(row*128 + ku*16));
            }
#pragma unroll
            for (int mi = 0; mi < 4; mi++)
#pragma unroll
                for (int nb = 0; nb < 4; nb++) {
                    mma_f16(acc[mi][nb*2+0], af[mi], &bf[nb][0]);
                    mma_f16(acc[mi][nb*2+1], af[mi], &bf[nb][2]);
                }
        }
    }

    // epilogue: warp 64x64 block
#pragma unroll
    for (int mi = 0; mi < 4; mi++) {
#pragma unroll
        for (int ni = 0; ni < 8; ni++) {
            int m0  = bm + wm*64 + mi*16 + g;
            int col = bn + wn*64 + ni*8 + 2*t;
            float b0 = bias[col], b1v = bias[col + 1];
            float v00 = acc[mi][ni][0] + b0, v01 = acc[mi][ni][1] + b1v;
            float v10 = acc[mi][ni][2] + b0, v11 = acc[mi][ni][3] + b1v;
            if (relu) {
                v00 = fmaxf(v00, 0.f); v01 = fmaxf(v01, 0.f);
                v10 = fmaxf(v10, 0.f); v11 = fmaxf(v11, 0.f);
            }
            if (Ch) {
                v00 *= oscale; v01 *= oscale; v10 *= oscale; v11 *= oscale;
                *(__half2*)(Ch + (size_t)m0*N + col)     = __floats2half2_rn(v00, v01);
                *(__half2*)(Ch + (size_t)(m0+8)*N + col) = __floats2half2_rn(v10, v11);
            } else {
                if (resid) {
                    float2 r0 = *(const float2*)(resid + (size_t)m0*N + col);
                    float2 r1 = *(const float2*)(resid + (size_t)(m0+8)*N + col);
                    v00 += r0.x; v01 += r0.y; v10 += r1.x; v11 += r1.y;
                }
                *(float2*)(Cf + (size_t)m0*N + col)     = make_float2(v00, v01);
                *(float2*)(Cf + (size_t)(m0+8)*N + col) = make_float2(v10, v11);
            }
        }
    }
}

__global__ __launch_bounds__(128, 2) void gemm_h_kernel(
    const __half* __restrict__ A, const __half* __restrict__ Wt,
    const float* __restrict__ bias, const float* __restrict__ resid,
    float* __restrict__ Cf, __half* __restrict__ Ch, int N, int K, int relu)
{
    gemm_h_core(A, Wt, bias, resid, Cf, Ch, N, K, relu, 1.0f,
                blockIdx.y * 128, blockIdx.x * 128);
}

struct TriH {
    const __half *W0, *W1, *W2;
    const float  *b0, *b1, *b2;
    __half *o0, *o1, *o2;
    float s0, s1, s2;
};
__global__ __launch_bounds__(128, 2) void gemm_qkv_kernel(
    const __half* __restrict__ A, TriH t)
{
    int z = blockIdx.z;
    const __half* W = (z == 0) ? t.W0 : (z == 1) ? t.W1 : t.W2;
    const float*  b = (z == 0) ? t.b0 : (z == 1) ? t.b1 : t.b2;
    __half*       o = (z == 0) ? t.o0 : (z == 1) ? t.o1 : t.o2;
    float        sc = (z == 0) ? t.s0 : (z == 1) ? t.s1 : t.s2;
    gemm_h_core(A, W, b, (const float*)0, (float*)0, o, D_MODEL, D_MODEL, 0, sc,
                blockIdx.y * 128, blockIdx.x * 128);
}

// ---------------- Sigmoid attention: 32q x 64keys warps, per-16key fusion --
// Block = (b, h, 256-query tile). 8 warps; warp w owns q rows [w*32, w*32+32)
// over ALL keys. Inner loop fuses S/sigmoid/PV per 16-key group: sacc is
// only 16 floats, ph 8 regs — S(ng+1) is independent of sig/PV(ng), so the
// scheduler overlaps the MUFU chain with tensor work. q carries scale/2.
// smem 80KB: Q 32K | K 3x8K | V 3x8K. 1 CTA/SM.
#define ATT_SMEM 81920

__global__ __launch_bounds__(256, 1) void hstu_attn_kernel(
    const __half* __restrict__ q, const __half* __restrict__ k,
    const __half* __restrict__ v, const float* __restrict__ xres,
    float* __restrict__ out)
{
    extern __shared__ __align__(128) char smemc[];
    const unsigned sb = (unsigned)__cvta_generic_to_shared(smemc);
    const unsigned sQ = sb, sK = sb + 32768, sV = sb + 32768 + 3*8192;

    const int tid = threadIdx.x, lane = tid & 31, wid = tid >> 5;
    const int g = lane >> 2, t = lane & 3;
    const int quad = lane >> 3, lr = lane & 7;
    const int qt = blockIdx.x, h = blockIdx.y, b = blockIdx.z;

    const size_t base = (size_t)b * SEQ * D_MODEL + (size_t)h * DH;
    const __half* qb = q + base;
    const __half* kb = k + base;
    const __half* vb = v + base;

    auto load_kv = [&](int kt, int s) {
#pragma unroll
        for (int i = 0; i < 2; i++) {
            int idx = i * 256 + tid;
            int r = idx >> 3, u = idx & 7;
            cp_async16(sK + s*8192 + sw128(r*128 + u*16),
                       (const char*)(kb + (size_t)(kt*64 + r) * D_MODEL) + u*16);
        }
#pragma unroll
        for (int i = 0; i < 2; i++) {
            int idx = i * 256 + tid;
            int r = idx >> 3, u = idx & 7;
            cp_async16(sV + s*8192 + sw128(r*128 + u*16),
                       (const char*)(vb + (size_t)(kt*64 + r) * D_MODEL) + u*16);
        }
        cp_commit();
    };

    // prologue: Q tile (256 rows, 32KB) rides with KV0's group; then KV1.
#pragma unroll
    for (int i = 0; i < 8; i++) {
        int idx = i * 256 + tid;
        int r = idx >> 3, u = idx & 7;
        cp_async16(sQ + sw128(r*128 + u*16),
                   (const char*)(qb + (size_t)(qt*256 + r) * D_MODEL) + u*16);
    }
    load_kv(0, 0);   // group 0 (Q + KV0)
    load_kv(1, 1);   // group 1

    // loop-invariant ldsm address components
    // sw128(row*128 + c) = row*128 + (c ^ ((row&7)*16)) for c < 128
    const unsigned q1_16 = (quad & 1) * 16;      // K col sel
    const unsigned q2_16 = (quad >> 1) * 16;     // V col sel
    unsigned kba[4], kxo[4];
#pragma unroll
    for (int ng = 0; ng < 4; ng++) {
        unsigned row = ng*16 + (quad >> 1)*8 + lr;
        kba[ng] = row * 128; kxo[ng] = (row & 7) * 16;
    }
    unsigned vba[4], vxo[4];
#pragma unroll
    for (int kc = 0; kc < 4; kc++) {
        unsigned row = kc*16 + (quad & 1)*8 + lr;
        vba[kc] = row * 128; vxo[kc] = (row & 7) * 16;
    }

    float oacc[2][8][4];
#pragma unroll
    for (int mi = 0; mi < 2; mi++)
#pragma unroll
        for (int j = 0; j < 8; j++)
#pragma unroll
            for (int r = 0; r < 4; r++) oacc[mi][j][r] = 0.f;

    unsigned qf[4][2][4];   // [kk][mi][reg] — 32 q rows
    const int NKT = SEQ / 64;

    for (int kt = 0; kt < NKT; kt++) {
        if (kt + 1 < NKT) cp_wait1(); else cp_wait0();
        __syncthreads();
        if (kt == 0) {
#pragma unroll
            for (int kk = 0; kk < 4; kk++)
#pragma unroll
                for (int mi = 0; mi < 2; mi++) {
                    unsigned row = wid*32 + mi*16 + (quad & 1)*8 + lr;
                    unsigned ku  = kk*2 + (quad >> 1);
                    ldsm4(qf[kk][mi][0], qf[kk][mi][1], qf[kk][mi][2], qf[kk][mi][3],
                          sQ + sw128(row*128 + ku*16));
                }
        }
        if (kt + 2 < NKT) load_kv(kt + 2, (kt + 2) % 3);

        unsigned bK = sK + (kt % 3) * 8192;
        unsigned bV = sV + (kt % 3) * 8192;

        // ---- fused per-16-key group: S_ng -> sigmoid_ng -> PV_ng ----
#pragma unroll
        for (int ng = 0; ng < 4; ng++) {
            // S: 32q x 16keys over d=64 (result = z/2)
            float sacc[2][2][4];
#pragma unroll
            for (int mi = 0; mi < 2; mi++)
#pragma unroll
                for (int nb = 0; nb < 2; nb++)
#pragma unroll
                    for (int r = 0; r < 4; r++) sacc[mi][nb][r] = 0.f;

#pragma unroll
            for (int kk = 0; kk < 4; kk++) {
                unsigned bf[4];
                ldsm4(bf[0], bf[1], bf[2], bf[3],
                      bK + kba[ng] + ((kk*32 + q1_16) ^ kxo[ng]));
#pragma unroll
                for (int mi = 0; mi < 2; mi++) {
                    mma_f16(sacc[mi][0], qf[kk][mi], &bf[0]);
                    mma_f16(sacc[mi][1], qf[kk][mi], &bf[2]);
                }
            }

            // sigmoid via tanh -> P as A-fragments (8 sig2)
            unsigned ph[2][4];
#pragma unroll
            for (int mi = 0; mi < 2; mi++) {
                ph[mi][0] = sig2(sacc[mi][0][0], sacc[mi][0][1]);
                ph[mi][1] = sig2(sacc[mi][0][2], sacc[mi][0][3]);
                ph[mi][2] = sig2(sacc[mi][1][0], sacc[mi][1][1]);
                ph[mi][3] = sig2(sacc[mi][1][2], sacc[mi][1][3]);
            }

            // PV: 32q x 64d over these 16 keys
#pragma unroll
            for (int nd = 0; nd < 4; nd++) {
                unsigned vf[4];
                ldsm4t(vf[0], vf[1], vf[2], vf[3],
                       bV + vba[ng] + ((nd*32 + q2_16) ^ vxo[ng]));
#pragma unroll
                for (int mi = 0; mi < 2; mi++) {
                    mma_f16(oacc[mi][2*nd+0], ph[mi], &vf[0]);
                    mma_f16(oacc[mi][2*nd+1], ph[mi], &vf[2]);
                }
            }
        }
    }

    // ---- epilogue: x2 = x + attn_out (fp32), warp-private rows ----
#pragma unroll
    for (int mi = 0; mi < 2; mi++) {
        int row0 = qt*256 + wid*32 + mi*16 + g;
#pragma unroll
        for (int nj = 0; nj < 8; nj++) {
            int col = nj*8 + 2*t;
            size_t i0 = base + (size_t)row0 * D_MODEL + col;
            size_t i1 = i0 + 8 * D_MODEL;
            float2 r0 = *(const float2*)(xres + i0);
            float2 r1 = *(const float2*)(xres + i1);
            *(float2*)(out + i0) = make_float2(r0.x + oacc[mi][nj][0],
                                               r0.y + oacc[mi][nj][1]);
            *(float2*)(out + i1) = make_float2(r1.x + oacc[mi][nj][2],
                                               r1.y + oacc[mi][nj][3]);
        }
    }
}

// ---------------- launch ----------------
extern "C" void kernel_launch(void* const* d_in, const int* in_sizes, int n_in,
                              void* d_out, int out_size)
{
    const float* x   = (const float*)d_in[0];
    const float* Wq  = (const float*)d_in[1];
    const float* bq  = (const float*)d_in[2];
    const float* Wk  = (const float*)d_in[3];
    const float* bk  = (const float*)d_in[4];
    const float* Wv  = (const float*)d_in[5];
    const float* bv  = (const float*)d_in[6];
    const float* W1  = (const float*)d_in[7];
    const float* b1  = (const float*)d_in[8];
    const float* W2  = (const float*)d_in[9];
    const float* b2  = (const float*)d_in[10];
    const float* g1  = (const float*)d_in[11];
    const float* be1 = (const float*)d_in[12];
    const float* g2  = (const float*)d_in[13];
    const float* be2 = (const float*)d_in[14];
    float* out = (float*)d_out;

    __half *xn, *qh, *kh, *vh, *xn2, *h1;
    float  *x2;
    __half *WqT, *WkT, *WvT, *W1T, *W2T;
    cudaGetSymbolAddress((void**)&xn,  g_xn);
    cudaGetSymbolAddress((void**)&qh,  g_q);
    cudaGetSymbolAddress((void**)&kh,  g_k);
    cudaGetSymbolAddress((void**)&vh,  g_v);
    cudaGetSymbolAddress((void**)&x2,  g_x2);
    cudaGetSymbolAddress((void**)&xn2, g_xn2);
    cudaGetSymbolAddress((void**)&h1,  g_h1);
    cudaGetSymbolAddress((void**)&WqT, g_WqT);
    cudaGetSymbolAddress((void**)&WkT, g_WkT);
    cudaGetSymbolAddress((void**)&WvT, g_WvT);
    cudaGetSymbolAddress((void**)&W1T, g_W1T);
    cudaGetSymbolAddress((void**)&W2T, g_W2T);

    cudaFuncSetAttribute(gemm_h_kernel,
                         cudaFuncAttributeMaxDynamicSharedMemorySize, GEMM_SMEM);
    cudaFuncSetAttribute(gemm_qkv_kernel,
                         cudaFuncAttributeMaxDynamicSharedMemorySize, GEMM_SMEM);
    cudaFuncSetAttribute(hstu_attn_kernel,
                         cudaFuncAttributeMaxDynamicSharedMemorySize, ATT_SMEM);

    // prepass: transpose + fp16-convert all weights (one launch)
    transpose_all_kernel<<<2816, 256>>>(Wq, Wk, Wv, W1, W2,
                                        WqT, WkT, WvT, W1T, W2T);

    dim3 lnb(32, 8);
    // LN1
    hstu_ln_kernel<<<MROWS/8, lnb>>>(x, g1, be1, xn);
    // QKV projections (merged; q pre-scaled by scale/2 for tanh sigmoid)
    TriH tri;
    tri.W0 = WqT; tri.W1 = WkT; tri.W2 = WvT;
    tri.b0 = bq;  tri.b1 = bk;  tri.b2 = bv;
    tri.o0 = qh;  tri.o1 = kh;  tri.o2 = vh;
    tri.s0 = 0.02209708691207961f; tri.s1 = 1.0f; tri.s2 = 1.0f;
    gemm_qkv_kernel<<<dim3(4, 64, 3), 128, GEMM_SMEM>>>(xn, tri);
    // sigmoid attention + residual
    hstu_attn_kernel<<<dim3(SEQ/256, NH, BATCH), 256, ATT_SMEM>>>(qh, kh, vh, x, x2);
    // LN2
    hstu_ln_kernel<<<MROWS/8, lnb>>>(x2, g2, be2, xn2);
    // FFN
    gemm_h_kernel<<<dim3(16, 64), 128, GEMM_SMEM>>>(xn2, W1T, b1, nullptr, nullptr, h1, 2048, 512, 1);
    gemm_h_kernel<<<dim3(4, 64), 128, GEMM_SMEM>>>(h1, W2T, b2, x2, out, nullptr, 512, 2048, 0);
}